// round 17
// baseline (speedup 1.0000x reference)
#include <cuda_runtime.h>
#include <cstdint>

// BestChangeLayer: B batches, 25x25 binary grids, 512 candidate 3x3 patterns,
// one Conway step on a 7x7 window, L1 error on inner 5x5 vs target,
// argmin(err + 0.5*noise), write winning pattern into x at (ry, rx).
//
// ONE WARP PER BATCH, zero barriers, zero shared memory.
// 64 threads/block = 2 independent warps. Each warp: gathers its windows,
// copies x->out, evaluates 16 patterns/lane as 4 CSA groups x 4 ripple
// variants, warp-shuffle argmin, patches the 3x3 winner.
//
// Bitboards: 7x7 packed in u64 at bit (r*8 + c).
// p = 16*lane + 4*g + v:
//   lane bits 4..0 -> board bits 18,19,20,26,27 (pattern elems k=0..4)
//   g bit1 -> bit 28 (k=5), g bit0 -> bit 34 (k=6)   [in anchor board]
//   v bit1 -> bit 35 (k=7), v bit0 -> bit 36 (k=8)   [ripple-added]

#define NPAT 512
typedef unsigned long long u64;

#define REDOR64(v) ( ((u64)__reduce_or_sync(0xffffffffu,(unsigned)((v) >> 32)) << 32) \
                   |  (u64)__reduce_or_sync(0xffffffffu,(unsigned)(v)) )

__global__ __launch_bounds__(64, 4)
void bcl_kernel(const float* __restrict__ x,
                const float* __restrict__ target,
                const float* __restrict__ noise,
                const int* __restrict__ ryp,
                const int* __restrict__ rxp,
                float* __restrict__ out,
                int B)
{
    const int lane = threadIdx.x & 31;
    const int warp = threadIdx.x >> 5;
    const int b    = blockIdx.x * 2 + warp;
    if (b >= B) return;                       // warp-uniform exit

    const float* __restrict__ xb = x + b * 625;
    const float* __restrict__ tb = target + b * 625;
    float* __restrict__ ob = out + b * 625;

    const int ry = *ryp, rx = *rxp;

    // ---- Gather both windows (periodic idx via conditional subtracts) ----
    u64 pf = 0, pt = 0;
    #pragma unroll
    for (int it = 0; it < 3; it++) {
        int item = lane + it * 32;
        if (item < 49) {
            int r = item / 7, c = item % 7;
            if (!(r >= 2 && r <= 4 && c >= 2 && c <= 4)) {
                int rr = ry + 23 + r; if (rr >= 25) rr -= 25; if (rr >= 25) rr -= 25;
                int cc = rx + 23 + c; if (cc >= 25) cc -= 25; if (cc >= 25) cc -= 25;
                if (xb[rr * 25 + cc] != 0.0f) pf |= 1ULL << (r * 8 + c);
            }
        } else if (item < 74) {
            int k = item - 49, r = k / 5, c = k % 5;
            int rr = ry + 24 + r; if (rr >= 25) rr -= 25; if (rr >= 25) rr -= 25;
            int cc = rx + 24 + c; if (cc >= 25) cc -= 25; if (cc >= 25) cc -= 25;
            if (tb[rr * 25 + cc] != 0.0f) pt |= 1ULL << ((r + 1) * 8 + (c + 1));
        }
    }
    const u64 fixedB = REDOR64(pf);
    const u64 targ   = REDOR64(pt);

    // ---- Copy x -> out (this warp owns the whole batch) ----
    #pragma unroll
    for (int i = 0; i < 20; i++) {
        int idx = lane + 32 * i;
        if (idx < 625) ob[idx] = xb[idx];
    }

    // Lane part of the pattern (elements k=0..4).
    const u64 base = ((u64)((lane >> 4) & 1) << 18)
                   | ((u64)((lane >> 3) & 1) << 19)
                   | ((u64)((lane >> 2) & 1) << 20)
                   | ((u64)((lane >> 1) & 1) << 26)
                   | ((u64)(lane & 1) << 27);

    const u64 M    = 0x007F7F7F7F7F7F7FULL;   // col-shift guard
    const u64 CROP = 0x00003E3E3E3E3E00ULL;   // rows 1..5, cols 1..5
    const u64 B35  = 1ULL << 35, B36 = 1ULL << 36;
    const u64 M35  = 0x00001C141C000000ULL;   // neighbors of cell (4,3)
    const u64 M36  = 0x0000382838000000ULL;   // neighbors of cell (4,4)

    u64 bestKey = ~0ULL;

#define FIN(NEXT, P, NZS)                                                    \
    {                                                                        \
        int err = __popcll(((NEXT) & CROP) ^ targ);                          \
        float sd = (float)err + (NZS) * 0.5f;                                \
        u64 key = ((u64)__float_as_uint(sd) << 32) | (unsigned)(P);          \
        if (key < bestKey) bestKey = key;                                    \
    }

    #pragma unroll
    for (int g = 0; g < 4; g++) {
        // Noise for patterns 16*lane + 4*g + {0..3}; 16B-aligned float4.
        const float4 nz = ((const float4*)noise)[b * 128 + 4 * lane + g];

        // Anchor board: includes g's center bits 28/34.
        const u64 Bg = fixedB | base
                     | ((u64)((g >> 1) & 1) << 28)
                     | ((u64)(g & 1) << 34);

        // CSA over the 8 neighbor planes -> bit-sliced count:
        //   cc0 = count bit0, cc1 = parity of weight-2 sum, hi = sum >= 2.
        // alive: cc1 & ~hi & (cc0 | cell).
        u64 n1 = (Bg << 1) & M, n2 = (Bg >> 1) & M;
        u64 n3 = Bg << 8,  n4 = Bg >> 8;
        u64 n5 = n1 << 8,  n6 = n1 >> 8;
        u64 n7 = n2 << 8,  n8 = n2 >> 8;

        u64 a1 = n1 ^ n2, b1 = n1 & n2;
        u64 a2 = n3 ^ n4, b2 = n3 & n4;
        u64 a3 = n5 ^ n6, b3 = n5 & n6;
        u64 a4 = n7 ^ n8, b4 = n7 & n8;

        u64 s1 = a1 ^ a2, t1 = a1 & a2;
        u64 s2 = a3 ^ a4, t2 = a3 & a4;
        u64 cc0 = s1 ^ s2, u0 = s1 & s2;

        u64 p1 = b1 ^ b2, q1 = b1 & b2;
        u64 p2 = b3 ^ b4, q2 = b3 & b4;
        u64 p3 = t1 ^ t2, q3 = t1 & t2;
        u64 r1 = p1 ^ p2, w1 = p1 & p2;
        u64 r2 = p3 ^ u0, w2 = p3 & u0;
        u64 cc1 = r1 ^ r2, w3 = r1 & r2;
        u64 hi = q1 | q2 | q3 | w1 | w2 | w3;

        const int pb = 16 * lane + 4 * g;

        { // v=0: no toggles
            u64 nx = cc1 & ~hi & (cc0 | Bg);
            FIN(nx, pb + 0, nz.x)
        }
        { // v=1: +bit36 -> ripple-add M36
            u64 k0 = cc0 & M36, a0v = cc0 ^ M36;
            u64 av = cc1 ^ k0,  h   = hi | (cc1 & k0);
            u64 nx = av & ~h & (a0v | Bg | B36);
            FIN(nx, pb + 1, nz.y)
        }
        { // v=2: +bit35 -> ripple-add M35
            u64 k0 = cc0 & M35, a0v = cc0 ^ M35;
            u64 av = cc1 ^ k0,  h   = hi | (cc1 & k0);
            u64 nx = av & ~h & (a0v | Bg | B35);
            FIN(nx, pb + 2, nz.z)
        }
        { // v=3: +bit35 then +bit36 (sequential ripple adds, exact)
            u64 k0 = cc0 & M35, a0v = cc0 ^ M35;
            u64 av = cc1 ^ k0,  h1  = hi | (cc1 & k0);
            u64 k1 = a0v & M36, g0  = a0v ^ M36;
            u64 gv = av ^ k1,   h2  = h1 | (av & k1);
            u64 nx = gv & ~h2 & (g0 | Bg | B35 | B36);
            FIN(nx, pb + 3, nz.w)
        }
    }
#undef FIN

    // Warp all-reduce argmin (packed key: value then first-index tiebreak).
    #pragma unroll
    for (int s = 16; s; s >>= 1) {
        u64 o = __shfl_xor_sync(0xffffffffu, bestKey, s);
        if (o < bestKey) bestKey = o;
    }

    __syncwarp();   // order copy stores before the patch overwrite

    if (lane < 9) {
        int best = (int)(unsigned)bestKey;
        float vv = ((best >> (8 - lane)) & 1) ? 1.0f : 0.0f;
        ob[(ry + lane / 3) * 25 + (rx + lane % 3)] = vv;
    }
}

extern "C" void kernel_launch(void* const* d_in, const int* in_sizes, int n_in,
                              void* d_out, int out_size)
{
    const float* x      = (const float*)d_in[0];
    const float* target = (const float*)d_in[1];
    const float* noise  = (const float*)d_in[2];
    const int*   ryp    = (const int*)d_in[3];
    const int*   rxp    = (const int*)d_in[4];
    float* out = (float*)d_out;

    int B = in_sizes[0] / 625;
    bcl_kernel<<<(B + 1) / 2, 64>>>(x, target, noise, ryp, rxp, out, B);
}